// round 15
// baseline (speedup 1.0000x reference)
#include <cuda_runtime.h>
#include <cuda_fp16.h>
#include <math.h>
#include <cstdint>

// ---------------------------------------------------------------------------
// Problem constants — 128-px CTAs, 2 CTAs/SM, K-split, NCH=48 (6 exact tiles)
// ---------------------------------------------------------------------------
#define C_      32
#define B_      8
#define INCH    201          // K*C*2 + K*K
#define KH      208          // K padded to 13 x 16 (halves)
#define NCH     48           // N per chunk = 6 n-tiles, zero padding
#define NCHUNKS 24           // 1152 / 48
#define FSTR_B  432          // feat/B row stride bytes (27 x 16B, conflict-free)
#define THREADS 256

// SMEM layout (bytes) — 103424 total, x2 CTAs = 206848
#define B0_OFF   0
#define BBYTES   (NCH*FSTR_B)               // 20736
#define B1_OFF   BBYTES                     // (scr borrows this in prologue)
#define BIAS_OFF (2*BBYTES)                 // 41472
#define YB_OFF   46080                      // feat (55296) overlaid by ybuf
#define FEAT_OFF YB_OFF
#define YSTR_H2  28                         // 8*28 mod 32 pattern: conflict-free
#define PLANE_B  (128*YSTR_H2*4)            // 14336 per kgrp plane
#define YHALF_B  (2*PLANE_B)                // 28672 per chunk buffer
#define SMEM_BYTES (YB_OFF + 2*YHALF_B)     // 103424

// ---------------------------------------------------------------------------
// Static scratch (no allocations)
// ---------------------------------------------------------------------------
__device__ __half g_wh[1152 * KH];   // BN-folded fp16 weights, K-padded
__device__ float  g_bias[1152];

// ---------------------------------------------------------------------------
// PTX helpers (sm_103 BASE features only)
// ---------------------------------------------------------------------------
__device__ __forceinline__ uint32_t su32(const void* p) {
    uint32_t a;
    asm("{ .reg .u64 t; cvta.to.shared.u64 t, %1; cvt.u32.u64 %0, t; }" : "=r"(a) : "l"(p));
    return a;
}
__device__ __forceinline__ void ldsm4(uint32_t* r, uint32_t a) {
    asm volatile("ldmatrix.sync.aligned.m8n8.x4.shared.b16 {%0,%1,%2,%3}, [%4];"
                 : "=r"(r[0]), "=r"(r[1]), "=r"(r[2]), "=r"(r[3]) : "r"(a));
}
__device__ __forceinline__ void ldsm2(uint32_t* r, uint32_t a) {
    asm volatile("ldmatrix.sync.aligned.m8n8.x2.shared.b16 {%0,%1}, [%2];"
                 : "=r"(r[0]), "=r"(r[1]) : "r"(a));
}
__device__ __forceinline__ void mma16816(float* c, const uint32_t* a, const uint32_t* b) {
    asm volatile("mma.sync.aligned.m16n8k16.row.col.f32.f16.f16.f32 "
                 "{%0,%1,%2,%3}, {%4,%5,%6,%7}, {%8,%9}, {%0,%1,%2,%3};"
                 : "+f"(c[0]), "+f"(c[1]), "+f"(c[2]), "+f"(c[3])
                 : "r"(a[0]), "r"(a[1]), "r"(a[2]), "r"(a[3]), "r"(b[0]), "r"(b[1]));
}
__device__ __forceinline__ void cpasync16(uint32_t dst, const void* src) {
    asm volatile("cp.async.cg.shared.global [%0], [%1], 16;" :: "r"(dst), "l"(src));
}
__device__ __forceinline__ void cpcommit() { asm volatile("cp.async.commit_group;"); }
__device__ __forceinline__ void cpwait1()  { asm volatile("cp.async.wait_group 1;" ::: "memory"); }

// ---------------------------------------------------------------------------
// Repack: fold BN into conv_w, convert fp16, pad K 201->208
// ---------------------------------------------------------------------------
__global__ void repack_kernel(const float* __restrict__ w,
                              const float* __restrict__ gamma,
                              const float* __restrict__ beta,
                              const float* __restrict__ mean,
                              const float* __restrict__ var) {
    int m = blockIdx.x;
    float sc = gamma[m] * rsqrtf(var[m] + 1e-5f);
    if (threadIdx.x == 0) g_bias[m] = beta[m] - mean[m] * sc;
    for (int k = threadIdx.x; k < KH; k += blockDim.x) {
        float v = (k < INCH) ? w[m * INCH + k] * sc : 0.f;
        g_wh[m * KH + k] = __float2half_rn(v);
    }
}

// Stage one 48-row N-chunk into SMEM (no pad rows needed: 48 = 6 tiles exact)
__device__ __forceinline__ void stage_b(uint32_t bufs, int n0, int tid) {
    for (int e = tid; e < NCH * 26; e += THREADS) {
        int r = e / 26, q = e - r * 26;
        cpasync16(bufs + r * FSTR_B + q * 16,
                  g_wh + (size_t)(n0 + r) * KH + q * 8);
    }
}

// ---------------------------------------------------------------------------
// Half-chunk GEMM pass: warp = M32 (2 mt) x 3 n-tiles over its K half.
// A register-resident; acc only 24 regs (two passes reuse them).
// ---------------------------------------------------------------------------
template <int NKS>
__device__ __forceinline__ void gemm_pass(const uint32_t afr[7][2][4], int ks0,
                                          uint32_t bpass, int lane,
                                          float acc[3][2][4]) {
    #pragma unroll
    for (int i = 0; i < NKS; ++i) {
        const int s4 = (ks0 + i) * 32 + ((lane >> 3) & 1) * 16;
        uint32_t bf[3][2];
        {   // tiles 0,1 of this pass (rows 0..15 rel)
            uint32_t ad = bpass + (uint32_t)((lane >> 4) * 8 + (lane & 7)) * FSTR_B + s4;
            uint32_t t4[4];
            ldsm4(t4, ad);
            bf[0][0] = t4[0]; bf[0][1] = t4[1];
            bf[1][0] = t4[2]; bf[1][1] = t4[3];
        }
        {   // tile 2 of this pass (rows 16..23 rel)
            uint32_t ad = bpass + (uint32_t)(16 + (lane & 7)) * FSTR_B + s4;
            ldsm2(bf[2], ad);
        }
        #pragma unroll
        for (int nt = 0; nt < 3; ++nt)
            #pragma unroll
            for (int mt = 0; mt < 2; ++mt)
                mma16816(acc[nt][mt], afr[i][mt], bf[nt]);
    }
}

// ---------------------------------------------------------------------------
// Fused epilogue for one channel c: thread = (pixel, uv-half).
// y spans 1-2 chunks; both ybuf buffers hold exactly those chunks.
// ---------------------------------------------------------------------------
__device__ __forceinline__ void epi_ch(int c, const char* smem,
                                       const float* __restrict__ x,
                                       float* __restrict__ out, int tid,
                                       int b, int oy0, int ox0) {
    const int p = tid >> 1, h = tid & 1;
    const int oyl = p >> 3, oxl = p & 7;
    const int oy = oy0 + oyl, ox = ox0 + oxl;
    const float* xc = x + ((size_t)(b * C_ + c) * 128) * 128;
    float ph[9];
    #pragma unroll
    for (int ki = 0; ki < 3; ++ki) {
        int iy = 2 * oy - 1 + ki;
        #pragma unroll
        for (int kj = 0; kj < 3; ++kj) {
            int ix = 2 * ox - 1 + kj;
            float v = 0.f;
            if ((unsigned)iy < 128u && (unsigned)ix < 128u)
                v = __ldg(xc + iy * 128 + ix);
            ph[ki * 3 + kj] = v;
        }
    }
    const float* bias_s = (const float*)(smem + BIAS_OFF);
    float o0 = 0.f, o1 = 0.f;
    #pragma unroll
    for (int kk = 0; kk < 9; ++kk) {
        const int n = 36 * c + 4 * kk + 2 * h;
        const int chunk = n / NCH;
        const int off = (n - chunk * NCH) >> 1;           // h2 offset 0..23
        const char* base = smem + YB_OFF + (chunk & 1) * YHALF_B;
        float2 ya = __half22float2(
            *(const __half2*)(base + (size_t)(p * YSTR_H2 + off) * 4));
        float2 yb = __half22float2(
            *(const __half2*)(base + PLANE_B + (size_t)(p * YSTR_H2 + off) * 4));
        float2 bb = *(const float2*)(bias_s + n);
        o0 += ph[kk] * fmaxf(ya.x + yb.x + bb.x, 0.f);
        o1 += ph[kk] * fmaxf(ya.y + yb.y + bb.y, 0.f);
    }
    const float inv9 = 1.f / 9.f;
    const size_t ob = ((size_t)(b * C_ + c) * 128 + 2 * oy + h) * 128 + 2 * ox;
    *(float2*)(out + ob) = make_float2(o0 * inv9, o1 * inv9);
}

// ---------------------------------------------------------------------------
// Main fused kernel: CTA = 128 pixels (16 oy x 8 ox), 2 CTAs/SM
// ---------------------------------------------------------------------------
__global__ __launch_bounds__(THREADS, 2)
void revo_hmma(const float* __restrict__ x, float* __restrict__ out) {
    extern __shared__ char smem[];
    __half* feat   = (__half*)(smem + FEAT_OFF);
    float*  scr    = (float*)(smem + B1_OFF);    // borrows B1 during prologue
    float*  bias_s = (float*)(smem + BIAS_OFF);
    const uint32_t sb = su32(smem);

    const int tid = threadIdx.x, lane = tid & 31, wid = tid >> 5;
    const int b = blockIdx.z, oy0 = blockIdx.y * 16, ox0 = blockIdx.x * 8;

    // stage weight chunk 0 early; bias -> smem
    stage_b(sb + B0_OFF, 0, tid);
    cpcommit();
    for (int e = tid; e < 1152; e += THREADS) bias_s[e] = g_bias[e];

    // ---- feat build from GLOBAL x, parallel over (pixel, 16-channel group) --
    {
        const int p = tid & 127, cg = tid >> 7;   // cg = 0/1
        const int oyl = p >> 3, oxl = p & 7;
        const int oy = oy0 + oyl, ox = ox0 + oxl;
        __half* fr = feat + p * (FSTR_B / 2);
        int iy[3], ix[3];
        bool oky[3], okx[3];
        #pragma unroll
        for (int k3 = 0; k3 < 3; ++k3) {
            iy[k3] = 2 * oy - 1 + k3; oky[k3] = (unsigned)iy[k3] < 128u;
            ix[k3] = 2 * ox - 1 + k3; okx[k3] = (unsigned)ix[k3] < 128u;
        }
        float cm[9];
        #pragma unroll
        for (int kk = 0; kk < 9; ++kk) cm[kk] = -3.402823466e38f;
        #pragma unroll
        for (int cc = 0; cc < 16; ++cc) {
            const int c = cg * 16 + cc;
            const float* xc = x + ((size_t)(b * C_ + c) * 128) * 128;
            float ph[9];
            #pragma unroll
            for (int ki = 0; ki < 3; ++ki)
                #pragma unroll
                for (int kj = 0; kj < 3; ++kj) {
                    float v = 0.f;
                    if (oky[ki] && okx[kj]) v = __ldg(xc + iy[ki] * 128 + ix[kj]);
                    ph[ki * 3 + kj] = v;
                }
            #pragma unroll
            for (int kk = 0; kk < 9; ++kk) cm[kk] = fmaxf(cm[kk], ph[kk]);
            #pragma unroll
            for (int j = 0; j < 3; ++j)
                fr[9 + c * 3 + j] =
                    __float2half_rn(fmaxf(fmaxf(ph[j], ph[3 + j]), ph[6 + j]));
            #pragma unroll
            for (int i = 0; i < 3; ++i)
                fr[105 + c * 3 + i] =
                    __float2half_rn(fmaxf(fmaxf(ph[3 * i], ph[3 * i + 1]), ph[3 * i + 2]));
        }
        #pragma unroll
        for (int kk = 0; kk < 9; ++kk) scr[p * 18 + cg * 9 + kk] = cm[kk];
    }
    __syncthreads();
    for (int e = tid; e < 128 * 9; e += THREADS) {
        int p = e / 9, kk = e - p * 9;
        feat[p * (FSTR_B / 2) + kk] =
            __float2half_rn(fmaxf(scr[p * 18 + kk], scr[p * 18 + 9 + kk]));
    }
    if (tid < 128) {
        #pragma unroll
        for (int k = INCH; k < KH; ++k)
            feat[tid * (FSTR_B / 2) + k] = __ushort_as_half(0);
    }
    __syncthreads();

    // warp roles: 4 M-groups (32 rows) x 2 K-groups (ksteps 0-6 / 7-12)
    const int mgrp = wid >> 1, kgrp = wid & 1;
    const int m0 = mgrp * 32;
    const int ks0 = kgrp * 7;
    const int nks = 7 - kgrp;          // 7 or 6
    const int g = lane >> 2, tg = lane & 3;

    // preload this warp's A fragments (<= 56 regs); feat dead afterwards
    uint32_t afr[7][2][4];
    #pragma unroll
    for (int i = 0; i < 7; ++i) {
        if (i < nks) {
            #pragma unroll
            for (int mt = 0; mt < 2; ++mt)
                ldsm4(afr[i][mt],
                      sb + FEAT_OFF + (uint32_t)(m0 + mt * 16 + (lane & 15)) * FSTR_B
                      + (ks0 + i) * 32 + (lane >> 4) * 16);
        }
    }
    __syncthreads();   // all afr loaded before ybuf overwrites feat region

    // ---- main loop: stage(t+1) | gemm(t) 2 passes | sync | epilogue | sync --
    for (int t = 0; t < NCHUNKS; ++t) {
        if (t + 1 < NCHUNKS)
            stage_b(sb + (((t + 1) & 1) ? B1_OFF : B0_OFF), (t + 1) * NCH, tid);
        cpcommit();
        cpwait1();

        const uint32_t bb = sb + ((t & 1) ? B1_OFF : B0_OFF);
        __half2* ybw = (__half2*)(smem + YB_OFF + (t & 1) * YHALF_B
                                  + kgrp * PLANE_B);
        #pragma unroll
        for (int pass = 0; pass < 2; ++pass) {
            float acc[3][2][4];
            #pragma unroll
            for (int i = 0; i < 3; ++i)
                #pragma unroll
                for (int j = 0; j < 2; ++j)
                    #pragma unroll
                    for (int k = 0; k < 4; ++k) acc[i][j][k] = 0.f;

            const uint32_t bpass = bb + pass * 24 * FSTR_B;
            if (kgrp == 0) gemm_pass<7>(afr, 0, bpass, lane, acc);
            else           gemm_pass<6>(afr, 7, bpass, lane, acc);

            #pragma unroll
            for (int nt = 0; nt < 3; ++nt) {
                const int h2i = (pass * 3 + nt) * 4 + tg;
                #pragma unroll
                for (int mt = 0; mt < 2; ++mt) {
                    const int p0 = m0 + mt * 16 + g;
                    ybw[p0 * YSTR_H2 + h2i] =
                        __floats2half2_rn(acc[nt][mt][0], acc[nt][mt][1]);
                    ybw[(p0 + 8) * YSTR_H2 + h2i] =
                        __floats2half2_rn(acc[nt][mt][2], acc[nt][mt][3]);
                }
            }
        }
        __syncthreads();   // ybuf(t) complete before epilogue reads it

        // epilogue: channels fully available through chunk t
        {
            const int c0 = (4 * t) / 3, c1 = (4 * (t + 1)) / 3;
            for (int c = c0; c < c1; ++c)
                epi_ch(c, smem, x, out, tid, b, oy0, ox0);
        }
        __syncthreads();   // epilogue reads done before buffers are reused
    }
}

// ---------------------------------------------------------------------------
extern "C" void kernel_launch(void* const* d_in, const int* in_sizes, int n_in,
                              void* d_out, int out_size) {
    const float* x   = (const float*)d_in[0];
    const float* cw  = (const float*)d_in[1];
    const float* gam = (const float*)d_in[2];
    const float* bet = (const float*)d_in[3];
    const float* mn  = (const float*)d_in[4];
    const float* vr  = (const float*)d_in[5];
    float* out       = (float*)d_out;

    cudaFuncSetAttribute(revo_hmma, cudaFuncAttributeMaxDynamicSharedMemorySize,
                         SMEM_BYTES);

    repack_kernel<<<1152, 128>>>(cw, gam, bet, mn, vr);
    dim3 grid(8, 4, B_);   // 256 CTAs, 2 resident per SM
    revo_hmma<<<grid, THREADS, SMEM_BYTES>>>(x, out);
}

// round 17
// speedup vs baseline: 1.5706x; 1.5706x over previous
#include <cuda_runtime.h>
#include <cuda_fp16.h>
#include <math.h>
#include <cstdint>

// ---------------------------------------------------------------------------
// Problem constants — 128-px CTAs, 2 CTAs/SM, warp K-split GEMM (R13 base)
// ---------------------------------------------------------------------------
#define C_      32
#define B_      8
#define INCH    201          // K*C*2 + K*K
#define KH      208          // K padded to 13 x 16 (halves)
#define NCH     36           // N per chunk (exactly 1 channel x 36)
#define NPAD    40           // padded to 5 n-tiles of 8
#define NCHUNKS 32           // 1152 / 36
#define FSTR_B  432          // feat/B row stride bytes (27 x 16B)
#define THREADS 256

// SMEM layout (bytes) — 89856 total, x2 CTAs = 179712
#define B0_OFF   0
#define BBYTES   (NPAD*FSTR_B)              // 17280
#define B1_OFF   BBYTES                     // (scr borrows this in prologue)
#define FEAT_OFF (2*BBYTES)                 // 34560
#define FEAT_BYTES (128*FSTR_B)             // 55296
#define SMEM_BYTES (FEAT_OFF + FEAT_BYTES)  // 89856
// ybuf reuses the feat region once A-fragments are register-resident:
#define YB_OFF   FEAT_OFF
#define YSTR_H2  20                         // conflict-free stores
#define YKG_H2   (128*YSTR_H2)              // 2560 half2 per kgrp plane
#define YKG_BYTES (YKG_H2*4)                // 10240
#define YBUF_BYTES (2*YKG_BYTES)            // 20480 per chunk buffer

// ---------------------------------------------------------------------------
// Static scratch (no allocations)
// ---------------------------------------------------------------------------
__device__ __half g_wh[1152 * KH];   // BN-folded fp16 weights, K-padded
__device__ float  g_bias[1152];

// ---------------------------------------------------------------------------
// PTX helpers (sm_103 BASE features only)
// ---------------------------------------------------------------------------
__device__ __forceinline__ uint32_t su32(const void* p) {
    uint32_t a;
    asm("{ .reg .u64 t; cvta.to.shared.u64 t, %1; cvt.u32.u64 %0, t; }" : "=r"(a) : "l"(p));
    return a;
}
__device__ __forceinline__ void ldsm4(uint32_t* r, uint32_t a) {
    asm volatile("ldmatrix.sync.aligned.m8n8.x4.shared.b16 {%0,%1,%2,%3}, [%4];"
                 : "=r"(r[0]), "=r"(r[1]), "=r"(r[2]), "=r"(r[3]) : "r"(a));
}
__device__ __forceinline__ void ldsm2(uint32_t* r, uint32_t a) {
    asm volatile("ldmatrix.sync.aligned.m8n8.x2.shared.b16 {%0,%1}, [%2];"
                 : "=r"(r[0]), "=r"(r[1]) : "r"(a));
}
__device__ __forceinline__ void mma16816(float* c, const uint32_t* a, const uint32_t* b) {
    asm volatile("mma.sync.aligned.m16n8k16.row.col.f32.f16.f16.f32 "
                 "{%0,%1,%2,%3}, {%4,%5,%6,%7}, {%8,%9}, {%0,%1,%2,%3};"
                 : "+f"(c[0]), "+f"(c[1]), "+f"(c[2]), "+f"(c[3])
                 : "r"(a[0]), "r"(a[1]), "r"(a[2]), "r"(a[3]), "r"(b[0]), "r"(b[1]));
}
__device__ __forceinline__ void cpasync16(uint32_t dst, const void* src) {
    asm volatile("cp.async.cg.shared.global [%0], [%1], 16;" :: "r"(dst), "l"(src));
}
__device__ __forceinline__ void cpcommit() { asm volatile("cp.async.commit_group;"); }
__device__ __forceinline__ void cpwait1()  { asm volatile("cp.async.wait_group 1;" ::: "memory"); }

// ---------------------------------------------------------------------------
// Repack: fold BN into conv_w, convert fp16, pad K 201->208
// ---------------------------------------------------------------------------
__global__ void repack_kernel(const float* __restrict__ w,
                              const float* __restrict__ gamma,
                              const float* __restrict__ beta,
                              const float* __restrict__ mean,
                              const float* __restrict__ var) {
    int m = blockIdx.x;
    float sc = gamma[m] * rsqrtf(var[m] + 1e-5f);
    if (threadIdx.x == 0) g_bias[m] = beta[m] - mean[m] * sc;
    for (int k = threadIdx.x; k < KH; k += blockDim.x) {
        float v = (k < INCH) ? w[m * INCH + k] * sc : 0.f;
        g_wh[m * KH + k] = __float2half_rn(v);
    }
}

// Stage one 36-row N-chunk — division-free mapping:
// lane = 16B-quad slot (26 of 32 active), warp = row (stride 8).
__device__ __forceinline__ void stage_b(uint32_t bufs, int n0, int tid) {
    const int q = tid & 31;
    if (q < 26) {
        const char* src = (const char*)(g_wh + (size_t)n0 * KH) + q * 16;
        const uint32_t dst = bufs + q * 16;
        const int r0 = tid >> 5;
        #pragma unroll
        for (int rr = 0; rr < 5; ++rr) {
            const int r = r0 + rr * 8;
            if (r < NCH) cpasync16(dst + r * FSTR_B, src + (size_t)r * (KH * 2));
        }
    }
}

// ---------------------------------------------------------------------------
// K-split chunk GEMM: warp = M32 (2 m-tiles) x 5 n-tiles over its K half.
// ---------------------------------------------------------------------------
__device__ __forceinline__ void gemm_chunk(const uint32_t afr[7][2][4],
                                           int ks0, int nks,
                                           uint32_t bbase, int lane,
                                           float acc[5][2][4]) {
    #pragma unroll
    for (int i = 0; i < 7; ++i) {
        if (i < nks) {
            const int s = ks0 + i;
            uint32_t bf[5][2];
            #pragma unroll
            for (int pq = 0; pq < 2; ++pq) {
                uint32_t ad = bbase
                            + (uint32_t)((pq * 2 + (lane >> 4)) * 8 + (lane & 7)) * FSTR_B
                            + s * 32 + ((lane >> 3) & 1) * 16;
                uint32_t t4[4];
                ldsm4(t4, ad);
                bf[2 * pq][0] = t4[0]; bf[2 * pq][1] = t4[1];
                bf[2 * pq + 1][0] = t4[2]; bf[2 * pq + 1][1] = t4[3];
            }
            {
                uint32_t ad = bbase + (uint32_t)(4 * 8 + (lane & 7)) * FSTR_B
                            + s * 32 + ((lane >> 3) & 1) * 16;
                ldsm2(bf[4], ad);
            }
            #pragma unroll
            for (int nt = 0; nt < 5; ++nt)
                #pragma unroll
                for (int mt = 0; mt < 2; ++mt)
                    mma16816(acc[nt][mt], afr[i][mt], bf[nt]);
        }
    }
}

// ---------------------------------------------------------------------------
// Epilogue split: (1) x-patch load (issued BEFORE GEMM to hide latency),
// (2) compute from prefetched patches + ybuf planes.
// ---------------------------------------------------------------------------
__device__ __forceinline__ void epi_loadx(int t, const float* __restrict__ x,
                                          float ph[9], int tid,
                                          int b, int oy0, int ox0) {
    const int p = tid >> 1;
    const int oyl = p >> 3, oxl = p & 7;
    const int oy = oy0 + oyl, ox = ox0 + oxl;
    const float* xc = x + ((size_t)(b * C_ + t) * 128) * 128;
    #pragma unroll
    for (int ki = 0; ki < 3; ++ki) {
        int iy = 2 * oy - 1 + ki;
        #pragma unroll
        for (int kj = 0; kj < 3; ++kj) {
            int ix = 2 * ox - 1 + kj;
            float v = 0.f;
            if ((unsigned)iy < 128u && (unsigned)ix < 128u)
                v = __ldg(xc + iy * 128 + ix);
            ph[ki * 3 + kj] = v;
        }
    }
}

__device__ __forceinline__ void epi_compute(int t, const char* ybase,
                                            const float ph[9],
                                            float* __restrict__ out, int tid,
                                            int b, int oy0, int ox0) {
    const int p = tid >> 1, h = tid & 1;
    const int oyl = p >> 3, oxl = p & 7;
    const int oy = oy0 + oyl, ox = ox0 + oxl;
    const __half2* yb0 = (const __half2*)ybase + p * YSTR_H2;
    const __half2* yb1 = yb0 + YKG_H2;
    const float* bs = g_bias + t * 36 + 2 * h;
    float o0 = 0.f, o1 = 0.f;
    #pragma unroll
    for (int kk = 0; kk < 9; ++kk) {
        const int idx = kk * 2 + h;
        const float pv = ph[kk];
        float2 a = __half22float2(yb0[idx]);
        float2 c = __half22float2(yb1[idx]);
        float2 bb = *(const float2*)(bs + kk * 4);
        o0 += pv * fmaxf(a.x + c.x + bb.x, 0.f);
        o1 += pv * fmaxf(a.y + c.y + bb.y, 0.f);
    }
    const float inv9 = 1.f / 9.f;
    const size_t ob = ((size_t)(b * C_ + t) * 128 + 2 * oy + h) * 128 + 2 * ox;
    *(float2*)(out + ob) = make_float2(o0 * inv9, o1 * inv9);
}

// ---------------------------------------------------------------------------
// Main fused kernel: CTA = 128 pixels (16 oy x 8 ox), 2 CTAs/SM
// ---------------------------------------------------------------------------
__global__ __launch_bounds__(THREADS, 2)
void revo_hmma(const float* __restrict__ x, float* __restrict__ out) {
    extern __shared__ char smem[];
    __half* feat = (__half*)(smem + FEAT_OFF);
    float*  scr  = (float*)(smem + B1_OFF);    // borrows B1 during prologue
    const uint32_t sb = su32(smem);

    const int tid = threadIdx.x, lane = tid & 31, wid = tid >> 5;
    const int b = blockIdx.z, oy0 = blockIdx.y * 16, ox0 = blockIdx.x * 8;

    // stage weight chunk 0 early
    stage_b(sb + B0_OFF, 0, tid);
    cpcommit();

    // ---- feat build from GLOBAL x, parallel over (pixel, 16-channel group) --
    {
        const int p = tid & 127, cg = tid >> 7;   // cg = 0/1
        const int oyl = p >> 3, oxl = p & 7;
        const int oy = oy0 + oyl, ox = ox0 + oxl;
        __half* fr = feat + p * (FSTR_B / 2);
        int iy[3], ix[3];
        bool oky[3], okx[3];
        #pragma unroll
        for (int k3 = 0; k3 < 3; ++k3) {
            iy[k3] = 2 * oy - 1 + k3; oky[k3] = (unsigned)iy[k3] < 128u;
            ix[k3] = 2 * ox - 1 + k3; okx[k3] = (unsigned)ix[k3] < 128u;
        }
        float cm[9];
        #pragma unroll
        for (int kk = 0; kk < 9; ++kk) cm[kk] = -3.402823466e38f;
        #pragma unroll
        for (int cc = 0; cc < 16; ++cc) {
            const int c = cg * 16 + cc;
            const float* xc = x + ((size_t)(b * C_ + c) * 128) * 128;
            float ph[9];
            #pragma unroll
            for (int ki = 0; ki < 3; ++ki)
                #pragma unroll
                for (int kj = 0; kj < 3; ++kj) {
                    float v = 0.f;
                    if (oky[ki] && okx[kj]) v = __ldg(xc + iy[ki] * 128 + ix[kj]);
                    ph[ki * 3 + kj] = v;
                }
            #pragma unroll
            for (int kk = 0; kk < 9; ++kk) cm[kk] = fmaxf(cm[kk], ph[kk]);
            #pragma unroll
            for (int j = 0; j < 3; ++j)
                fr[9 + c * 3 + j] =
                    __float2half_rn(fmaxf(fmaxf(ph[j], ph[3 + j]), ph[6 + j]));
            #pragma unroll
            for (int i = 0; i < 3; ++i)
                fr[105 + c * 3 + i] =
                    __float2half_rn(fmaxf(fmaxf(ph[3 * i], ph[3 * i + 1]), ph[3 * i + 2]));
        }
        #pragma unroll
        for (int kk = 0; kk < 9; ++kk) scr[p * 18 + cg * 9 + kk] = cm[kk];
    }
    __syncthreads();
    for (int e = tid; e < 128 * 9; e += THREADS) {
        int p = e / 9, kk = e - p * 9;
        feat[p * (FSTR_B / 2) + kk] =
            __float2half_rn(fmaxf(scr[p * 18 + kk], scr[p * 18 + 9 + kk]));
    }
    if (tid < 128) {
        #pragma unroll
        for (int k = INCH; k < KH; ++k)
            feat[tid * (FSTR_B / 2) + k] = __ushort_as_half(0);
    }
    // zero pad rows 36..39 of both B buffers (scr no longer needed)
    for (int e = tid; e < 2 * 4 * 27; e += THREADS) {
        int buf = e / 108, r = (e / 27) & 3, q = e % 27;
        *(uint4*)(smem + (buf ? B1_OFF : B0_OFF) + (36 + r) * FSTR_B + q * 16) =
            make_uint4(0, 0, 0, 0);
    }
    __syncthreads();

    // warp roles: 4 M-groups (32 rows) x 2 K-groups (ksteps 0-6 / 7-12)
    const int mgrp = wid >> 1, kgrp = wid & 1;
    const int m0 = mgrp * 32;
    const int ks0 = kgrp * 7;
    const int nks = 7 - kgrp;          // 7 or 6
    const int g = lane >> 2, tg = lane & 3;

    // preload this warp's A fragments (<= 56 regs); feat dead afterwards
    uint32_t afr[7][2][4];
    #pragma unroll
    for (int i = 0; i < 7; ++i) {
        if (i < nks) {
            #pragma unroll
            for (int mt = 0; mt < 2; ++mt)
                ldsm4(afr[i][mt],
                      sb + FEAT_OFF + (uint32_t)(m0 + mt * 16 + (lane & 15)) * FSTR_B
                      + (ks0 + i) * 32 + (lane >> 4) * 16);
        }
    }
    __syncthreads();   // all afr loaded before ybuf overwrites feat region

    // ---- pipelined loop: stage(t+1) | prefetch x | GEMM(t) | epilogue(t-1) --
    for (int t = 0; t < NCHUNKS; ++t) {
        if (t + 1 < NCHUNKS)
            stage_b(sb + (((t + 1) & 1) ? B1_OFF : B0_OFF), (t + 1) * NCH, tid);
        cpcommit();
        cpwait1();

        // prefetch epilogue(t-1) x-patches: LDG latency hides under the GEMM
        float ph[9];
        if (t > 0) epi_loadx(t - 1, x, ph, tid, b, oy0, ox0);

        const uint32_t bb = sb + ((t & 1) ? B1_OFF : B0_OFF);
        float acc[5][2][4];
        #pragma unroll
        for (int i = 0; i < 5; ++i)
            #pragma unroll
            for (int j = 0; j < 2; ++j)
                #pragma unroll
                for (int k = 0; k < 4; ++k) acc[i][j][k] = 0.f;

        gemm_chunk(afr, ks0, nks, bb, lane, acc);

        // K-partial C frags -> this kgrp's ybuf plane (fp16)
        __half2* ybw = (__half2*)(smem + YB_OFF + (t & 1) * YBUF_BYTES
                                  + kgrp * YKG_BYTES);
        #pragma unroll
        for (int nt = 0; nt < 5; ++nt) {
            const int h2i = nt * 4 + tg;
            #pragma unroll
            for (int mt = 0; mt < 2; ++mt) {
                const int p0 = m0 + mt * 16 + g;
                ybw[p0 * YSTR_H2 + h2i] =
                    __floats2half2_rn(acc[nt][mt][0], acc[nt][mt][1]);
                ybw[(p0 + 8) * YSTR_H2 + h2i] =
                    __floats2half2_rn(acc[nt][mt][2], acc[nt][mt][3]);
            }
        }

        if (t > 0)
            epi_compute(t - 1, smem + YB_OFF + ((t - 1) & 1) * YBUF_BYTES,
                        ph, out, tid, b, oy0, ox0);
        __syncthreads();
    }
    {
        float ph[9];
        epi_loadx(NCHUNKS - 1, x, ph, tid, b, oy0, ox0);
        epi_compute(NCHUNKS - 1, smem + YB_OFF + ((NCHUNKS - 1) & 1) * YBUF_BYTES,
                    ph, out, tid, b, oy0, ox0);
    }
}

// ---------------------------------------------------------------------------
extern "C" void kernel_launch(void* const* d_in, const int* in_sizes, int n_in,
                              void* d_out, int out_size) {
    const float* x   = (const float*)d_in[0];
    const float* cw  = (const float*)d_in[1];
    const float* gam = (const float*)d_in[2];
    const float* bet = (const float*)d_in[3];
    const float* mn  = (const float*)d_in[4];
    const float* vr  = (const float*)d_in[5];
    float* out       = (float*)d_out;

    cudaFuncSetAttribute(revo_hmma, cudaFuncAttributeMaxDynamicSharedMemorySize,
                         SMEM_BYTES);

    repack_kernel<<<1152, 128>>>(cw, gam, bet, mn, vr);
    dim3 grid(8, 4, B_);   // 256 CTAs, 2 resident per SM -> single wave
    revo_hmma<<<grid, THREADS, SMEM_BYTES>>>(x, out);
}